// round 1
// baseline (speedup 1.0000x reference)
#include <cuda_runtime.h>

// FeedForwardQuantum:
//   theta[b,s] = dot(x[b,s,:], W1[0,:]) + b1[0]
//   q[b,s]     = cos(theta) * cos(phi)
//   out[b,s,d] = q[b,s] * W2[d,0] + b2[d]
//
// EMBED_DIM = 1024, tokens = B*S = 8*4096 = 32768.
// Pure HBM streaming: 128 MiB in (x) + 128 MiB out. One CTA per token,
// 256 threads, one float4 load + one float4 store per thread.

#define EMBED_DIM 1024
#define THREADS   256   // EMBED_DIM / 4 float4 lanes

__global__ __launch_bounds__(THREADS, 8)
void ffq_kernel(const float4* __restrict__ x,
                const float4* __restrict__ W1,
                const float*  __restrict__ b1,
                const float*  __restrict__ phi,
                const float4* __restrict__ W2,
                const float4* __restrict__ b2,
                float4* __restrict__ out)
{
    const int token = blockIdx.x;
    const int tid   = threadIdx.x;
    const long base = (long)token * THREADS + tid;

    // --- dot(x_row, W1) ---
    const float4 xv = x[base];
    const float4 wv = W1[tid];          // 4 KiB, L1/L2 resident
    float p = xv.x * wv.x + xv.y * wv.y + xv.z * wv.z + xv.w * wv.w;

    // warp reduce
    #pragma unroll
    for (int o = 16; o > 0; o >>= 1)
        p += __shfl_xor_sync(0xffffffffu, p, o);

    __shared__ float warp_sums[THREADS / 32];
    if ((tid & 31) == 0) warp_sums[tid >> 5] = p;
    __syncthreads();

    // every thread sums the 8 warp partials (broadcast LDS, cheap)
    float theta = b1[0];
    #pragma unroll
    for (int i = 0; i < THREADS / 32; i++)
        theta += warp_sums[i];

    const float q = __cosf(theta) * __cosf(phi[0]);
    // __cosf has ~2^-22 max abs err on |x| < ~50; theta = dot of 1024 N(0,1)
    // with U(-1/32,1/32) weights -> |theta| ~ O(1..20), safe. Use precise cosf
    // instead if rel_err marginal.

    // --- out = q * W2 + b2 ---
    const float4 w2 = W2[tid];
    const float4 bb = b2[tid];
    float4 o;
    o.x = fmaf(q, w2.x, bb.x);
    o.y = fmaf(q, w2.y, bb.y);
    o.z = fmaf(q, w2.z, bb.z);
    o.w = fmaf(q, w2.w, bb.w);
    out[base] = o;
}

extern "C" void kernel_launch(void* const* d_in, const int* in_sizes, int n_in,
                              void* d_out, int out_size)
{
    // metadata order: x, W1, b1, phi, W2, b2
    const float4* x   = (const float4*)d_in[0];
    const float4* W1  = (const float4*)d_in[1];
    const float*  b1  = (const float*) d_in[2];
    const float*  phi = (const float*) d_in[3];
    const float4* W2  = (const float4*)d_in[4];
    const float4* b2  = (const float4*)d_in[5];
    float4* out = (float4*)d_out;

    const int tokens = in_sizes[0] / EMBED_DIM;   // 32768
    ffq_kernel<<<tokens, THREADS>>>(x, W1, b1, phi, W2, b2, out);
}

// round 2
// speedup vs baseline: 1.0412x; 1.0412x over previous
#include <cuda_runtime.h>

// FeedForwardQuantum: warp-per-token streaming kernel.
//   theta = dot(x_row, W1) + b1 ; out = cos(theta)*cos(phi) * W2 + b2
// EMBED_DIM=1024 (= 256 float4), tokens = 32768.
//
// Each warp owns one token row: 8 float4 loads/thread front-batched
// (32 KB in flight per SM at 32 warps -> covers ~15 KB HBM BW*latency
// product), shuffle-only reduction (no smem / no __syncthreads),
// 8 float4 stores. __ldcs/__stcs: pure streaming, no reuse of x/out.

#define EMBED_F4       256   // float4s per token row
#define WARPS_PER_CTA    8
#define THREADS        (WARPS_PER_CTA * 32)
#define F4_PER_THREAD  (EMBED_F4 / 32)   // 8

__global__ __launch_bounds__(THREADS)
void ffq_kernel(const float4* __restrict__ x,
                const float4* __restrict__ W1,
                const float*  __restrict__ b1,
                const float*  __restrict__ phi,
                const float4* __restrict__ W2,
                const float4* __restrict__ b2,
                float4* __restrict__ out)
{
    const int warp = threadIdx.x >> 5;
    const int lane = threadIdx.x & 31;
    const long token = (long)blockIdx.x * WARPS_PER_CTA + warp;
    const long rbase = token * EMBED_F4 + lane;

    // Front-batch all 8 x loads -> max memory-level parallelism.
    float4 xv[F4_PER_THREAD];
    #pragma unroll
    for (int i = 0; i < F4_PER_THREAD; i++)
        xv[i] = __ldcs(&x[rbase + 32 * i]);

    // Dot with W1 (4 KiB, L1-resident after first touch).
    float p = 0.0f;
    #pragma unroll
    for (int i = 0; i < F4_PER_THREAD; i++) {
        const float4 wv = W1[lane + 32 * i];
        p = fmaf(xv[i].x, wv.x,
            fmaf(xv[i].y, wv.y,
            fmaf(xv[i].z, wv.z,
            fmaf(xv[i].w, wv.w, p))));
    }

    // Warp-only reduction: no smem, no block barrier.
    #pragma unroll
    for (int o = 16; o > 0; o >>= 1)
        p += __shfl_xor_sync(0xffffffffu, p, o);

    const float theta = p + b1[0];
    const float q = __cosf(theta) * __cosf(phi[0]);

    // out = q * W2 + b2  (W2/b2 L1-resident), streaming stores.
    #pragma unroll
    for (int i = 0; i < F4_PER_THREAD; i++) {
        const float4 w2 = W2[lane + 32 * i];
        const float4 bb = b2[lane + 32 * i];
        float4 o;
        o.x = fmaf(q, w2.x, bb.x);
        o.y = fmaf(q, w2.y, bb.y);
        o.z = fmaf(q, w2.z, bb.z);
        o.w = fmaf(q, w2.w, bb.w);
        __stcs(&out[rbase + 32 * i], o);
    }
}

extern "C" void kernel_launch(void* const* d_in, const int* in_sizes, int n_in,
                              void* d_out, int out_size)
{
    const float4* x   = (const float4*)d_in[0];
    const float4* W1  = (const float4*)d_in[1];
    const float*  b1  = (const float*) d_in[2];
    const float*  phi = (const float*) d_in[3];
    const float4* W2  = (const float4*)d_in[4];
    const float4* b2  = (const float4*)d_in[5];
    float4* out = (float4*)d_out;

    const int tokens = in_sizes[0] / (EMBED_F4 * 4);   // 32768
    ffq_kernel<<<tokens / WARPS_PER_CTA, THREADS>>>(x, W1, b1, phi, W2, b2, out);
}